// round 15
// baseline (speedup 1.0000x reference)
#include <cuda_runtime.h>
#include <cuda_fp16.h>
#include <math.h>
#include <stdint.h>

#define NN 20000
#define EE 320000
#define ITERS 10
#define MBK 157
#define FRAGH 8192   // u32 words per 128x128 fp16 A-fragment block

#define PDL_TRIGGER() asm volatile("griddepcontrol.launch_dependents;")
#define PDL_WAIT()    asm volatile("griddepcontrol.wait;")

// ---------------- device scratch ----------------
__device__ float g_P0[NN * 256], g_P1[NN * 256], g_y[NN * 256];
__device__ __align__(16) uint32_t g_Ahf[MBK * FRAGH], g_Alf[MBK * FRAGH];  // h hi/lo frag (z0 during setup)
__device__ __align__(16) uint32_t g_Ghf[MBK * FRAGH], g_Glf[MBK * FRAGH];  // agg hi/lo frag (z1 during setup)
__device__ float g_a1[NN], g_a2[NN];
__device__ int   g_rf[NN];           // reach flag (any incident alpha >= 0.4)
__device__ int   g_deg[NN], g_indptr[NN + 1], g_cursor[NN];
__device__ int   g_csr_src[EE], g_csr_eid[EE];
__device__ __align__(16) uint32_t g_B1h[2 * 24576];  // h-rows of [W1|W2], frag layout (hi,hi,lo)
__device__ __align__(16) uint32_t g_BPh[2 * 24576];  // z-rows of [W1|W2]
__device__ __align__(16) uint32_t g_B2h[24576];      // Wout

// ---------------- helpers ----------------
__device__ __forceinline__ uint32_t smem_u32(const void* p) {
    uint32_t a;
    asm("{ .reg .u64 t; cvta.to.shared.u64 t, %1; cvt.u32.u64 %0, t; }" : "=r"(a) : "l"(p));
    return a;
}
__device__ __forceinline__ void cpasync16(uint32_t dst, const void* src) {
    asm volatile("cp.async.cg.shared.global [%0], [%1], 16;" :: "r"(dst), "l"(src));
}
__device__ __forceinline__ uint32_t pk2h(float a, float b) {
    __half2 h = __floats2half2_rn(a, b);
    return *(uint32_t*)&h;
}
__device__ __forceinline__ float hi16(float v) { return __half2float(__float2half_rn(v)); }
__device__ __forceinline__ void mma_f16(float* c, const uint32_t* a, const uint32_t* b) {
    asm volatile(
        "mma.sync.aligned.m16n8k16.row.col.f32.f16.f16.f32 "
        "{%0,%1,%2,%3}, {%4,%5,%6,%7}, {%8,%9}, {%0,%1,%2,%3};"
        : "+f"(c[0]), "+f"(c[1]), "+f"(c[2]), "+f"(c[3])
        : "r"(a[0]), "r"(a[1]), "r"(a[2]), "r"(a[3]), "r"(b[0]), "r"(b[1]));
}
__device__ __forceinline__ float sigmoidf_fast(float t) {
    return 1.0f / (1.0f + __expf(-t));
}
// word index of (row rv in [0,128), even col cc in [0,128)) inside one A-frag block
__device__ __forceinline__ int fidxh(int rv, int cc) {
    int ks = cc >> 4, kk = cc & 15, mt = rv >> 4, r = rv & 15;
    int slot = (r >> 3) + ((kk >> 3) << 1);
    int lane = ((r & 7) << 2) | ((kk & 7) >> 1);
    return ((ks * 8 + mt) * 32 + lane) * 4 + slot;
}

// ---------------- setup kernels ----------------
__global__ void k_init() {
    PDL_TRIGGER();
    int t = blockIdx.x * blockDim.x + threadIdx.x;
    if (t < NN) { g_deg[t] = 0; g_rf[t] = 0; }
}
__global__ void k_hist(const int* __restrict__ ei) {
    PDL_TRIGGER();
    int e = blockIdx.x * blockDim.x + threadIdx.x;
    int d = (e < EE) ? ei[EE + e] : 0;
    PDL_WAIT();
    if (e < EE) atomicAdd(&g_deg[d], 1);
}
__global__ void k_scan() {
    PDL_TRIGGER();
    PDL_WAIT();
    __shared__ int sh[1024];
    int t = threadIdx.x;
    const int CH = 20;
    int base = t * CH, s = 0;
    for (int i = 0; i < CH; i++) { int idx = base + i; if (idx < NN) s += g_deg[idx]; }
    sh[t] = s;
    __syncthreads();
    for (int o = 1; o < 1024; o <<= 1) {
        int v = (t >= o) ? sh[t - o] : 0;
        __syncthreads();
        sh[t] += v;
        __syncthreads();
    }
    int run = (t == 0) ? 0 : sh[t - 1];
    for (int i = 0; i < CH; i++) {
        int idx = base + i;
        if (idx < NN) { g_indptr[idx] = run; g_cursor[idx] = run; run += g_deg[idx]; }
    }
    if (t == 1023) g_indptr[NN] = sh[1023];
}

// fused: fp16 B-table packing + z0/z1 frag prep (pre-wait), then CSR scatter (post-wait)
__global__ void k_fused(const int* __restrict__ ei,
                        const float* __restrict__ W1, const float* __restrict__ W2,
                        const float* __restrict__ Wout,
                        const float* __restrict__ pos, const float* __restrict__ Wenc,
                        const float* __restrict__ benc) {
    PDL_TRIGGER();
    int t0 = blockIdx.x * blockDim.x + threadIdx.x;
    int gs = gridDim.x * blockDim.x;
    for (int t = t0; t < 122880; t += gs) {
        int which, w;
        if (t < 49152) { which = 0; w = t; }
        else if (t < 98304) { which = 1; w = t - 49152; }
        else { which = 2; w = t - 98304; }
        int cb = w / 24576;
        int rem = w % 24576;
        int gks = rem >> 10;
        int r = rem & 1023;
        int nt = r >> 6;
        int r2 = r & 63;
        int lane = r2 >> 1, slot = r2 & 1;
        int n = cb * 128 + nt * 8 + (lane >> 2);
        int k0 = (gks & 7) * 16 + (lane & 3) * 2 + slot * 8;
        int term = gks >> 3;   // 0,1 = hi ; 2 = lo
        float v0, v1;
        if (which == 0) {
            v0 = (n < 128) ? W1[(128 + k0) * 128 + n] : W2[(128 + k0) * 128 + (n - 128)];
            v1 = (n < 128) ? W1[(129 + k0) * 128 + n] : W2[(129 + k0) * 128 + (n - 128)];
        } else if (which == 1) {
            v0 = (n < 128) ? W1[k0 * 128 + n] : W2[k0 * 128 + (n - 128)];
            v1 = (n < 128) ? W1[(k0 + 1) * 128 + n] : W2[(k0 + 1) * 128 + (n - 128)];
        } else {
            v0 = Wout[k0 * 128 + n];
            v1 = Wout[(k0 + 1) * 128 + n];
        }
        uint32_t word;
        if (term < 2) word = pk2h(v0, v1);
        else          word = pk2h(v0 - hi16(v0), v1 - hi16(v1));
        if (which == 0) g_B1h[w] = word;
        else if (which == 1) g_BPh[w] = word;
        else g_B2h[w] = word;
    }
    for (int t = t0; t < NN * 32; t += gs) {
        int v = t >> 5, c0 = (t & 31) << 2;
        float p = pos[v];
        float4 w0 = *(const float4*)(Wenc + c0);
        float4 w1 = *(const float4*)(Wenc + 128 + c0);
        float4 b = *(const float4*)(benc + c0);
        int base = (v >> 7) * FRAGH;
        int rv = v & 127;
        int i0 = base + fidxh(rv, c0);
        int i1 = base + fidxh(rv, c0 + 2);
#pragma unroll
        for (int rr = 0; rr < 2; rr++) {
            float rf = (float)rr;
            float z0 = fmaxf(fmaf(p, w0.x, fmaf(rf, w1.x, b.x)), 0.0f);
            float z1 = fmaxf(fmaf(p, w0.y, fmaf(rf, w1.y, b.y)), 0.0f);
            float z2 = fmaxf(fmaf(p, w0.z, fmaf(rf, w1.z, b.z)), 0.0f);
            float z3 = fmaxf(fmaf(p, w0.w, fmaf(rf, w1.w, b.w)), 0.0f);
            uint32_t* dh = rr ? g_Ghf : g_Ahf;
            uint32_t* dl = rr ? g_Glf : g_Alf;
            dh[i0] = pk2h(z0, z1);
            dl[i0] = pk2h(z0 - hi16(z0), z1 - hi16(z1));
            dh[i1] = pk2h(z2, z3);
            dl[i1] = pk2h(z2 - hi16(z2), z3 - hi16(z3));
        }
    }
    PDL_WAIT();
    for (int e = t0; e < EE; e += gs) {
        int d = ei[EE + e];
        int slot = atomicAdd(&g_cursor[d], 1);
        g_csr_src[slot] = ei[e];
        g_csr_eid[slot] = e;
    }
}

// ---------------- 64-row fp16-split GEMM tile, 3-stage cp.async pipeline ----------------
// smem (bytes): A buf b at b*8192 [0,24576); B buf b at 24576 + b*16384 [24576,73728)
// MODE 0: raw fp32 -> Cout + conditional y init by s-select
// MODE 1: acc + P_sel(g_rf) -> g_y
template <int MODE>
__device__ __forceinline__ void gemm_tile64(
    float* smem, int tb, int cb,
    const uint32_t* __restrict__ Ah, const uint32_t* __restrict__ Al,
    const uint32_t* __restrict__ Bh, float* __restrict__ Cout,
    const float* __restrict__ sflag, int ysel, bool b_prewait)
{
    const int tid = threadIdx.x, lane = tid & 31, wid = tid >> 5;
    const int wm = wid & 1, wn = wid >> 1;
    const int mb = tb >> 1, h = tb & 1;
    const uint32_t sbase = smem_u32(smem);
    uint32_t* smemU = (uint32_t*)smem;
    float acc[2][4][4];
#pragma unroll
    for (int i = 0; i < 2; i++)
#pragma unroll
        for (int j = 0; j < 4; j++)
#pragma unroll
            for (int q = 0; q < 4; q++) acc[i][j][q] = 0.0f;

    auto stageA = [&](int c, int buf) {
        const uint32_t* As = (((c >> 1) == 1) ? Al : Ah) + mb * FRAGH + (c & 1) * 4096;
        uint32_t da = sbase + buf * 8192;
#pragma unroll
        for (int i = 0; i < 2; i++) {
            int f = tid + 256 * i;
            int blk = f >> 5, lg = f & 31;
            cpasync16(da + f * 16, As + ((blk >> 2) * 8 + 4 * h + (blk & 3)) * 128 + lg * 4);
        }
    };
    auto stageB = [&](int c, int buf) {
        const uint32_t* Bs = Bh + cb * 24576 + c * 4096;
        uint32_t db = sbase + 24576 + buf * 16384;
#pragma unroll
        for (int i = 0; i < 4; i++) {
            int f = tid + 256 * i;
            cpasync16(db + f * 16, Bs + f * 4);
        }
    };

    if (b_prewait) {
        stageB(0, 0);
        PDL_WAIT();
    } else {
        PDL_WAIT();
        stageB(0, 0);
    }
    stageA(0, 0);
    asm volatile("cp.async.commit_group;");
    stageA(1, 1);
    stageB(1, 1);
    asm volatile("cp.async.commit_group;");
    for (int c = 0; c < 6; c++) {
        int buf = c % 3;
        if (c < 4) {
            int nb = (c + 2) % 3;
            stageA(c + 2, nb);
            stageB(c + 2, nb);
            asm volatile("cp.async.commit_group;");
            asm volatile("cp.async.wait_group 2;");
        } else if (c == 4) {
            asm volatile("cp.async.wait_group 1;");
        } else {
            asm volatile("cp.async.wait_group 0;");
        }
        __syncthreads();
        const uint32_t* Ab = smemU + buf * 2048;
        const uint32_t* Bb = smemU + 6144 + buf * 4096;
#pragma unroll
        for (int ks = 0; ks < 4; ks++) {
            uint4 a[2];
            uint2 b[4];
#pragma unroll
            for (int mt = 0; mt < 2; mt++)
                a[mt] = *(const uint4*)(Ab + ((ks * 4 + wm * 2 + mt) * 32 + lane) * 4);
#pragma unroll
            for (int nt = 0; nt < 4; nt++)
                b[nt] = *(const uint2*)(Bb + ((ks * 16 + wn * 4 + nt) * 32 + lane) * 2);
#pragma unroll
            for (int mt = 0; mt < 2; mt++)
#pragma unroll
                for (int nt = 0; nt < 4; nt++)
                    mma_f16(acc[mt][nt], (const uint32_t*)&a[mt], (const uint32_t*)&b[nt]);
        }
        __syncthreads();
    }

    const int row0 = tb * 64, colofs = cb * 128;
#pragma unroll
    for (int mt = 0; mt < 2; mt++) {
        int rva = wm * 32 + mt * 16 + (lane >> 2);
        int rvb = rva + 8;
        int ga = row0 + rva, gb = row0 + rvb;
        const float *Pa = nullptr, *Pb = nullptr;
        bool ya = false, yb = false;
        if (MODE == 1) {
            if (ga < NN) Pa = g_rf[ga] ? g_P1 : g_P0;
            if (gb < NN) Pb = g_rf[gb] ? g_P1 : g_P0;
        } else {
            if (ga < NN) ya = (sflag[ga] > 0.5f) == (ysel != 0);
            if (gb < NN) yb = (sflag[gb] > 0.5f) == (ysel != 0);
        }
#pragma unroll
        for (int nt = 0; nt < 4; nt++) {
            int col = wn * 32 + nt * 8 + ((lane & 3) << 1);
            float c0 = acc[mt][nt][0], c1 = acc[mt][nt][1];
            float c2 = acc[mt][nt][2], c3 = acc[mt][nt][3];
            if (MODE == 0) {
                if (ga < NN) {
                    float2 v = {c0, c1};
                    *(float2*)(Cout + (size_t)ga * 256 + colofs + col) = v;
                    if (ya) *(float2*)(g_y + (size_t)ga * 256 + colofs + col) = v;
                }
                if (gb < NN) {
                    float2 v = {c2, c3};
                    *(float2*)(Cout + (size_t)gb * 256 + colofs + col) = v;
                    if (yb) *(float2*)(g_y + (size_t)gb * 256 + colofs + col) = v;
                }
            } else {
                if (ga < NN) {
                    float2 pv = *(const float2*)(Pa + (size_t)ga * 256 + colofs + col);
                    float2 v = {c0 + pv.x, c1 + pv.y};
                    *(float2*)(g_y + (size_t)ga * 256 + colofs + col) = v;
                }
                if (gb < NN) {
                    float2 pv = *(const float2*)(Pb + (size_t)gb * 256 + colofs + col);
                    float2 v = {c2 + pv.x, c3 + pv.y};
                    *(float2*)(g_y + (size_t)gb * 256 + colofs + col) = v;
                }
            }
        }
    }
}

// ---------------- GEMM2, 64-row tiles, 3-stage pipeline; fused decoder gemv ----------------
__device__ __forceinline__ void gemm2_tile64(
    float* smem, int tb,
    const float* __restrict__ bias, const float* __restrict__ Wdec)
{
    const int tid = threadIdx.x, lane = tid & 31, wid = tid >> 5;
    const int wm = wid & 1, wn = wid >> 1;
    const int mb = tb >> 1, h = tb & 1;
    const uint32_t sbase = smem_u32(smem);
    uint32_t* smemU = (uint32_t*)smem;
    float acc[2][4][4];
#pragma unroll
    for (int i = 0; i < 2; i++)
#pragma unroll
        for (int j = 0; j < 4; j++)
#pragma unroll
            for (int q = 0; q < 4; q++) acc[i][j][q] = 0.0f;

    auto stageA = [&](int c, int buf) {
        const uint32_t* As = (((c >> 1) == 1) ? g_Glf : g_Ghf) + mb * FRAGH + (c & 1) * 4096;
        uint32_t da = sbase + buf * 8192;
#pragma unroll
        for (int i = 0; i < 2; i++) {
            int f = tid + 256 * i;
            int blk = f >> 5, lg = f & 31;
            cpasync16(da + f * 16, As + ((blk >> 2) * 8 + 4 * h + (blk & 3)) * 128 + lg * 4);
        }
    };
    auto stageB = [&](int c, int buf) {
        const uint32_t* Bs = g_B2h + c * 4096;
        uint32_t db = sbase + 24576 + buf * 16384;
#pragma unroll
        for (int i = 0; i < 4; i++) {
            int f = tid + 256 * i;
            cpasync16(db + f * 16, Bs + f * 4);
        }
    };

    stageB(0, 0);
    PDL_WAIT();
    stageA(0, 0);
    asm volatile("cp.async.commit_group;");
    stageA(1, 1);
    stageB(1, 1);
    asm volatile("cp.async.commit_group;");
    for (int c = 0; c < 6; c++) {
        int buf = c % 3;
        if (c < 4) {
            int nb = (c + 2) % 3;
            stageA(c + 2, nb);
            stageB(c + 2, nb);
            asm volatile("cp.async.commit_group;");
            asm volatile("cp.async.wait_group 2;");
        } else if (c == 4) {
            asm volatile("cp.async.wait_group 1;");
        } else {
            asm volatile("cp.async.wait_group 0;");
        }
        __syncthreads();
        const uint32_t* Ab = smemU + buf * 2048;
        const uint32_t* Bb = smemU + 6144 + buf * 4096;
#pragma unroll
        for (int ks = 0; ks < 4; ks++) {
            uint4 a[2];
            uint2 b[4];
#pragma unroll
            for (int mt = 0; mt < 2; mt++)
                a[mt] = *(const uint4*)(Ab + ((ks * 4 + wm * 2 + mt) * 32 + lane) * 4);
#pragma unroll
            for (int nt = 0; nt < 4; nt++)
                b[nt] = *(const uint2*)(Bb + ((ks * 16 + wn * 4 + nt) * 32 + lane) * 2);
#pragma unroll
            for (int mt = 0; mt < 2; mt++)
#pragma unroll
                for (int nt = 0; nt < 4; nt++)
                    mma_f16(acc[mt][nt], (const uint32_t*)&a[mt], (const uint32_t*)&b[nt]);
        }
        __syncthreads();
    }

    const int row0 = mb * 128 + h * 64;
    float s1r[4], s2r[4];
#pragma unroll
    for (int i = 0; i < 4; i++) { s1r[i] = 0.0f; s2r[i] = 0.0f; }

#pragma unroll
    for (int mt = 0; mt < 2; mt++) {
        int rva = wm * 32 + mt * 16 + (lane >> 2);
        int rvb = rva + 8;
        int ga = row0 + rva, gb = row0 + rvb;
#pragma unroll
        for (int nt = 0; nt < 4; nt++) {
            int col = wn * 32 + nt * 8 + ((lane & 3) << 1);
            float c0 = acc[mt][nt][0], c1 = acc[mt][nt][1];
            float c2 = acc[mt][nt][2], c3 = acc[mt][nt][3];
            float b0 = bias[col], b1 = bias[col + 1];
            float w10 = Wdec[col], w11 = Wdec[col + 1];
            float w20 = Wdec[128 + col], w21 = Wdec[128 + col + 1];
            float v0 = fmaxf(c0 + b0, 0.0f), v1 = fmaxf(c1 + b1, 0.0f);
            float v2 = fmaxf(c2 + b0, 0.0f), v3 = fmaxf(c3 + b1, 0.0f);
            s1r[mt * 2 + 0] += v0 * w10 + v1 * w11;
            s2r[mt * 2 + 0] += v0 * w20 + v1 * w21;
            s1r[mt * 2 + 1] += v2 * w10 + v3 * w11;
            s2r[mt * 2 + 1] += v2 * w20 + v3 * w21;
            if (ga < NN) {
                int i0 = mb * FRAGH + fidxh(h * 64 + rva, col);
                g_Ahf[i0] = pk2h(v0, v1);
                g_Alf[i0] = pk2h(v0 - hi16(v0), v1 - hi16(v1));
            }
            if (gb < NN) {
                int i0 = mb * FRAGH + fidxh(h * 64 + rvb, col);
                g_Ahf[i0] = pk2h(v2, v3);
                g_Alf[i0] = pk2h(v2 - hi16(v2), v3 - hi16(v3));
            }
        }
    }
    {
        float* red = smem;
        int t3 = lane & 3;
#pragma unroll
        for (int mt = 0; mt < 2; mt++)
#pragma unroll
            for (int hf = 0; hf < 2; hf++) {
                int rl = wm * 32 + mt * 16 + (lane >> 2) + hf * 8;
                red[rl * 16 + wn * 4 + t3] = s1r[mt * 2 + hf];
                red[1024 + rl * 16 + wn * 4 + t3] = s2r[mt * 2 + hf];
            }
        __syncthreads();
        if (tid < 64) {
            int ga = row0 + tid;
            if (ga < NN) {
                float a = 0.0f, b = 0.0f;
#pragma unroll
                for (int q = 0; q < 16; q++) { a += red[tid * 16 + q]; b += red[1024 + tid * 16 + q]; }
                g_a1[ga] = a;
                g_a2[ga] = b;
            }
        }
        __syncthreads();
    }
}

// setup: blocks [0, 4*MBK) -> P0 (A=z0-frag), rest -> P1 (A=z1-frag); epilogue inits y by s-select
__global__ __launch_bounds__(256, 3) void k_setupgemm(const float* __restrict__ s) {
    PDL_TRIGGER();
    extern __shared__ float smem[];
    int b = blockIdx.x;
    if (b < 4 * MBK)
        gemm_tile64<0>(smem, b >> 1, b & 1, g_Ahf, g_Alf, g_BPh, g_P0, s, 0, false);
    else {
        b -= 4 * MBK;
        gemm_tile64<0>(smem, b >> 1, b & 1, g_Ghf, g_Glf, g_BPh, g_P1, s, 1, false);
    }
}
__global__ __launch_bounds__(256, 3) void k_gemm1() {
    PDL_TRIGGER();
    extern __shared__ float smem[];
    gemm_tile64<1>(smem, blockIdx.x, blockIdx.y, g_Ahf, g_Alf, g_B1h, nullptr, nullptr, 0, true);
}
__global__ __launch_bounds__(256, 3) void k_gemm2(const float* __restrict__ bout,
                                                  const float* __restrict__ Wdec) {
    PDL_TRIGGER();
    extern __shared__ float smem[];
    gemm2_tile64(smem, blockIdx.x, bout, Wdec);
}

// ---------------- iteration kernels ----------------
// 2 warps per node: segment max over half the channels; relu(max+y2+b); frag write; rf zero
__global__ void k_segmax(const float* __restrict__ bmsg) {
    PDL_TRIGGER();
    int u = (blockIdx.x * blockDim.x + threadIdx.x) >> 5;
    int lane = threadIdx.x & 31;
    if (u >= NN * 2) return;
    int w = u >> 1, hf = u & 1;
    int beg = g_indptr[w], end = g_indptr[w + 1];
    int c0 = hf * 64 + lane * 2;
    PDL_WAIT();
    float m0 = -INFINITY, m1 = -INFINITY;
    int j = beg;
    for (; j + 3 < end; j += 4) {
        int s0 = g_csr_src[j], s1 = g_csr_src[j + 1];
        int s2 = g_csr_src[j + 2], s3 = g_csr_src[j + 3];
        float2 v0 = *(const float2*)(g_y + (size_t)s0 * 256 + c0);
        float2 v1 = *(const float2*)(g_y + (size_t)s1 * 256 + c0);
        float2 v2 = *(const float2*)(g_y + (size_t)s2 * 256 + c0);
        float2 v3 = *(const float2*)(g_y + (size_t)s3 * 256 + c0);
        m0 = fmaxf(fmaxf(m0, fmaxf(v0.x, v1.x)), fmaxf(v2.x, v3.x));
        m1 = fmaxf(fmaxf(m1, fmaxf(v0.y, v1.y)), fmaxf(v2.y, v3.y));
    }
    for (; j < end; j++) {
        int s0 = g_csr_src[j];
        float2 v0 = *(const float2*)(g_y + (size_t)s0 * 256 + c0);
        m0 = fmaxf(m0, v0.x);
        m1 = fmaxf(m1, v0.y);
    }
    float o0, o1;
    if (end > beg) {
        float2 y2 = *(const float2*)(g_y + (size_t)w * 256 + 128 + c0);
        float2 b = *(const float2*)(bmsg + c0);
        o0 = fmaxf(m0 + y2.x + b.x, 0.0f);
        o1 = fmaxf(m1 + y2.y + b.y, 0.0f);
    } else { o0 = 0.0f; o1 = 0.0f; }
    int i0 = (w >> 7) * FRAGH + fidxh(w & 127, c0);
    g_Ghf[i0] = pk2h(o0, o1);
    g_Glf[i0] = pk2h(o0 - hi16(o0), o1 - hi16(o1));
    if (hf == 0 && lane == 0) g_rf[w] = 0;
}

// 2 edges per thread, vectorized; edge indices pre-loaded before PDL wait
__global__ void k_alpha(const int* __restrict__ ei, const float* __restrict__ bdec,
                        float* __restrict__ out, int it) {
    PDL_TRIGGER();
    int e = (blockIdx.x * blockDim.x + threadIdx.x) * 2;
    if (e >= EE) return;
    int2 sv = *(const int2*)(ei + e);
    int2 dv = *(const int2*)(ei + EE + e);
    float bd = bdec[0];
    PDL_WAIT();
    float t0 = g_a1[sv.x] + g_a2[dv.x] + bd;
    float t1 = g_a1[sv.y] + g_a2[dv.y] + bd;
    float al0 = sigmoidf_fast(t0);
    float al1 = sigmoidf_fast(t1);
    float2 o = {al0, al1};
    *(float2*)(out + (size_t)it * EE + e) = o;
    if (al0 >= 0.4f) { g_rf[sv.x] = 1; g_rf[dv.x] = 1; }
    if (al1 >= 0.4f) { g_rf[sv.y] = 1; g_rf[dv.y] = 1; }
}

__global__ void k_final(const float* __restrict__ bdec, float* __restrict__ out) {
    int w = (blockIdx.x * blockDim.x + threadIdx.x) >> 5;
    int lane = threadIdx.x & 31;
    if (w >= NN) return;
    int beg = g_indptr[w], end = g_indptr[w + 1];
    float bd = bdec[0];
    PDL_WAIT();
    if (lane == 0) out[(size_t)10 * EE + w] = g_rf[w] ? 1.0f : 0.0f;
    float a2v = g_a2[w];
    float ba = -1.0f;
    int beid = 0x7FFFFFFF, bsrc = w;
    for (int j = beg + lane; j < end; j += 32) {
        int sv = g_csr_src[j], eid = g_csr_eid[j];
        float t = g_a1[sv] + a2v + bd;
        float al = sigmoidf_fast(t);
        if (al > ba || (al == ba && eid < beid)) { ba = al; beid = eid; bsrc = sv; }
    }
#pragma unroll
    for (int o = 16; o; o >>= 1) {
        float oa = __shfl_xor_sync(0xFFFFFFFFu, ba, o);
        int oe = __shfl_xor_sync(0xFFFFFFFFu, beid, o);
        int os = __shfl_xor_sync(0xFFFFFFFFu, bsrc, o);
        if (oa > ba || (oa == ba && oe < beid)) { ba = oa; beid = oe; bsrc = os; }
    }
    if (lane == 0) out[(size_t)10 * EE + NN + w] = (float)((end > beg) ? bsrc : w);
}

// ---------------- host ----------------
static void launch_pdl(const void* func, dim3 grid, dim3 block, size_t smem, void** args) {
    cudaLaunchConfig_t cfg = {};
    cfg.gridDim = grid;
    cfg.blockDim = block;
    cfg.dynamicSmemBytes = smem;
    cfg.stream = 0;
    cudaLaunchAttribute attr;
    attr.id = cudaLaunchAttributeProgrammaticStreamSerialization;
    attr.val.programmaticStreamSerializationAllowed = 1;
    cfg.attrs = &attr;
    cfg.numAttrs = 1;
    cudaLaunchKernelExC(&cfg, func, args);
}

extern "C" void kernel_launch(void* const* d_in, const int* in_sizes, int n_in,
                              void* d_out, int out_size) {
    const float* pos  = (const float*)d_in[0];
    const float* s    = (const float*)d_in[1];
    const int*   ei   = (const int*)d_in[2];
    const float* Wenc = (const float*)d_in[3];
    const float* benc = (const float*)d_in[4];
    const float* W1   = (const float*)d_in[5];
    const float* W2   = (const float*)d_in[6];
    const float* bmsg = (const float*)d_in[7];
    const float* Wout = (const float*)d_in[8];
    const float* bout = (const float*)d_in[9];
    const float* Wdec = (const float*)d_in[10];
    const float* bdec = (const float*)d_in[11];
    float* out = (float*)d_out;

    const int SMEM3 = 73728;   // A 24KB + B 48KB, triple-buffered
    cudaFuncSetAttribute(k_setupgemm, cudaFuncAttributeMaxDynamicSharedMemorySize, SMEM3);
    cudaFuncSetAttribute(k_gemm1, cudaFuncAttributeMaxDynamicSharedMemorySize, SMEM3);
    cudaFuncSetAttribute(k_gemm2, cudaFuncAttributeMaxDynamicSharedMemorySize, SMEM3);

    const int TB = 256;
    k_init<<<(NN + TB - 1) / TB, TB>>>();
    {
        void* args[] = {(void*)&ei};
        launch_pdl((const void*)k_hist, dim3((EE + TB - 1) / TB), dim3(TB), 0, args);
    }
    launch_pdl((const void*)k_scan, dim3(1), dim3(1024), 0, nullptr);
    {
        void* args[] = {(void*)&ei, (void*)&W1, (void*)&W2, (void*)&Wout,
                        (void*)&pos, (void*)&Wenc, (void*)&benc};
        launch_pdl((const void*)k_fused, dim3(1024), dim3(TB), 0, args);
    }
    {
        void* args[] = {(void*)&s};
        launch_pdl((const void*)k_setupgemm, dim3(8 * MBK), dim3(TB), SMEM3, args);
    }

    for (int it = 0; it < ITERS; it++) {
        if (it > 0)
            launch_pdl((const void*)k_gemm1, dim3(2 * MBK, 2), dim3(TB), SMEM3, nullptr);
        {
            void* args[] = {(void*)&bmsg};
            launch_pdl((const void*)k_segmax, dim3((NN * 2 + 7) / 8), dim3(TB), 0, args);
        }
        {
            void* args[] = {(void*)&bout, (void*)&Wdec};
            launch_pdl((const void*)k_gemm2, dim3(2 * MBK), dim3(TB), SMEM3, args);
        }
        {
            int itv = it;
            void* args[] = {(void*)&ei, (void*)&bdec, (void*)&out, (void*)&itv};
            launch_pdl((const void*)k_alpha, dim3((EE / 2 + TB - 1) / TB), dim3(TB), 0, args);
        }
    }
    {
        void* args[] = {(void*)&bdec, (void*)&out};
        launch_pdl((const void*)k_final, dim3((NN + 7) / 8), dim3(TB), 0, args);
    }
}

// round 16
// speedup vs baseline: 1.0561x; 1.0561x over previous
#include <cuda_runtime.h>
#include <cuda_fp16.h>
#include <math.h>
#include <stdint.h>

#define NN 20000
#define EE 320000
#define ITERS 10
#define MBK 157
#define FRAGH 8192   // u32 words per 128x128 fp16 A-fragment block

#define PDL_TRIGGER() asm volatile("griddepcontrol.launch_dependents;")
#define PDL_WAIT()    asm volatile("griddepcontrol.wait;")

// ---------------- device scratch ----------------
__device__ float g_P0[NN * 256], g_P1[NN * 256], g_y[NN * 256];
__device__ __align__(16) uint32_t g_Ahf[MBK * FRAGH], g_Alf[MBK * FRAGH];  // h hi/lo frag (z0 during setup)
__device__ __align__(16) uint32_t g_Ghf[MBK * FRAGH], g_Glf[MBK * FRAGH];  // agg hi/lo frag (z1 during setup)
__device__ float g_a1[NN], g_a2[NN];
__device__ int   g_rf[NN];           // reach flag (any incident alpha >= 0.4)
__device__ int   g_deg[NN], g_indptr[NN + 1], g_cursor[NN];
__device__ int   g_csr_src[EE], g_csr_eid[EE];
__device__ __align__(16) uint32_t g_B1h[2 * 24576];  // h-rows of [W1|W2], frag layout (hi,hi,lo)
__device__ __align__(16) uint32_t g_BPh[2 * 24576];  // z-rows of [W1|W2]
__device__ __align__(16) uint32_t g_B2h[24576];      // Wout

// ---------------- helpers ----------------
__device__ __forceinline__ uint32_t smem_u32(const void* p) {
    uint32_t a;
    asm("{ .reg .u64 t; cvta.to.shared.u64 t, %1; cvt.u32.u64 %0, t; }" : "=r"(a) : "l"(p));
    return a;
}
__device__ __forceinline__ void cpasync16(uint32_t dst, const void* src) {
    asm volatile("cp.async.cg.shared.global [%0], [%1], 16;" :: "r"(dst), "l"(src));
}
__device__ __forceinline__ uint32_t pk2h(float a, float b) {
    __half2 h = __floats2half2_rn(a, b);
    return *(uint32_t*)&h;
}
__device__ __forceinline__ float hi16(float v) { return __half2float(__float2half_rn(v)); }
__device__ __forceinline__ void mma_f16(float* c, const uint32_t* a, const uint32_t* b) {
    asm volatile(
        "mma.sync.aligned.m16n8k16.row.col.f32.f16.f16.f32 "
        "{%0,%1,%2,%3}, {%4,%5,%6,%7}, {%8,%9}, {%0,%1,%2,%3};"
        : "+f"(c[0]), "+f"(c[1]), "+f"(c[2]), "+f"(c[3])
        : "r"(a[0]), "r"(a[1]), "r"(a[2]), "r"(a[3]), "r"(b[0]), "r"(b[1]));
}
__device__ __forceinline__ float sigmoidf_fast(float t) {
    return 1.0f / (1.0f + __expf(-t));
}
// word index of (row rv in [0,128), even col cc in [0,128)) inside one A-frag block
__device__ __forceinline__ int fidxh(int rv, int cc) {
    int ks = cc >> 4, kk = cc & 15, mt = rv >> 4, r = rv & 15;
    int slot = (r >> 3) + ((kk >> 3) << 1);
    int lane = ((r & 7) << 2) | ((kk & 7) >> 1);
    return ((ks * 8 + mt) * 32 + lane) * 4 + slot;
}

// ---------------- setup kernels ----------------
__global__ void k_init() {
    int t = blockIdx.x * blockDim.x + threadIdx.x;
    if (t < NN) { g_deg[t] = 0; g_rf[t] = 0; }
}
__global__ void k_hist(const int* __restrict__ ei) {
    int e = blockIdx.x * blockDim.x + threadIdx.x;
    if (e < EE) atomicAdd(&g_deg[ei[EE + e]], 1);
}
__global__ void k_scan() {
    __shared__ int sh[1024];
    int t = threadIdx.x;
    const int CH = 20;
    int base = t * CH, s = 0;
    for (int i = 0; i < CH; i++) { int idx = base + i; if (idx < NN) s += g_deg[idx]; }
    sh[t] = s;
    __syncthreads();
    for (int o = 1; o < 1024; o <<= 1) {
        int v = (t >= o) ? sh[t - o] : 0;
        __syncthreads();
        sh[t] += v;
        __syncthreads();
    }
    int run = (t == 0) ? 0 : sh[t - 1];
    for (int i = 0; i < CH; i++) {
        int idx = base + i;
        if (idx < NN) { g_indptr[idx] = run; g_cursor[idx] = run; run += g_deg[idx]; }
    }
    if (t == 1023) g_indptr[NN] = sh[1023];
}

// fused: CSR scatter + fp16 B-table packing + z0/z1 frag prep
__global__ void k_fused(const int* __restrict__ ei,
                        const float* __restrict__ W1, const float* __restrict__ W2,
                        const float* __restrict__ Wout,
                        const float* __restrict__ pos, const float* __restrict__ Wenc,
                        const float* __restrict__ benc) {
    int t0 = blockIdx.x * blockDim.x + threadIdx.x;
    int gs = gridDim.x * blockDim.x;
    for (int e = t0; e < EE; e += gs) {
        int d = ei[EE + e];
        int slot = atomicAdd(&g_cursor[d], 1);
        g_csr_src[slot] = ei[e];
        g_csr_eid[slot] = e;
    }
    for (int t = t0; t < 122880; t += gs) {
        int which, w;
        if (t < 49152) { which = 0; w = t; }
        else if (t < 98304) { which = 1; w = t - 49152; }
        else { which = 2; w = t - 98304; }
        int cb = w / 24576;
        int rem = w % 24576;
        int gks = rem >> 10;
        int r = rem & 1023;
        int nt = r >> 6;
        int r2 = r & 63;
        int lane = r2 >> 1, slot = r2 & 1;
        int n = cb * 128 + nt * 8 + (lane >> 2);
        int k0 = (gks & 7) * 16 + (lane & 3) * 2 + slot * 8;
        int term = gks >> 3;   // 0,1 = hi ; 2 = lo
        float v0, v1;
        if (which == 0) {
            v0 = (n < 128) ? W1[(128 + k0) * 128 + n] : W2[(128 + k0) * 128 + (n - 128)];
            v1 = (n < 128) ? W1[(129 + k0) * 128 + n] : W2[(129 + k0) * 128 + (n - 128)];
        } else if (which == 1) {
            v0 = (n < 128) ? W1[k0 * 128 + n] : W2[k0 * 128 + (n - 128)];
            v1 = (n < 128) ? W1[(k0 + 1) * 128 + n] : W2[(k0 + 1) * 128 + (n - 128)];
        } else {
            v0 = Wout[k0 * 128 + n];
            v1 = Wout[(k0 + 1) * 128 + n];
        }
        uint32_t word;
        if (term < 2) word = pk2h(v0, v1);
        else          word = pk2h(v0 - hi16(v0), v1 - hi16(v1));
        if (which == 0) g_B1h[w] = word;
        else if (which == 1) g_BPh[w] = word;
        else g_B2h[w] = word;
    }
    for (int t = t0; t < NN * 32; t += gs) {
        int v = t >> 5, c0 = (t & 31) << 2;
        float p = pos[v];
        float4 w0 = *(const float4*)(Wenc + c0);
        float4 w1 = *(const float4*)(Wenc + 128 + c0);
        float4 b = *(const float4*)(benc + c0);
        int base = (v >> 7) * FRAGH;
        int rv = v & 127;
        int i0 = base + fidxh(rv, c0);
        int i1 = base + fidxh(rv, c0 + 2);
#pragma unroll
        for (int rr = 0; rr < 2; rr++) {
            float rf = (float)rr;
            float z0 = fmaxf(fmaf(p, w0.x, fmaf(rf, w1.x, b.x)), 0.0f);
            float z1 = fmaxf(fmaf(p, w0.y, fmaf(rf, w1.y, b.y)), 0.0f);
            float z2 = fmaxf(fmaf(p, w0.z, fmaf(rf, w1.z, b.z)), 0.0f);
            float z3 = fmaxf(fmaf(p, w0.w, fmaf(rf, w1.w, b.w)), 0.0f);
            uint32_t* dh = rr ? g_Ghf : g_Ahf;
            uint32_t* dl = rr ? g_Glf : g_Alf;
            dh[i0] = pk2h(z0, z1);
            dl[i0] = pk2h(z0 - hi16(z0), z1 - hi16(z1));
            dh[i1] = pk2h(z2, z3);
            dl[i1] = pk2h(z2 - hi16(z2), z3 - hi16(z3));
        }
    }
}

// ---------------- 64-row fp16-split GEMM tile (64x128, K_ext=384, 256 thr, 48KB smem dbuf) ----------------
// PDL: B chunk 0 is staged pre-wait (setup-constant), A chunk 0 post-wait.
// MODE 0: raw fp32 -> Cout + conditional y init by s-select
// MODE 1: acc + P_sel(g_rf) -> g_y
template <int MODE>
__device__ __forceinline__ void gemm_tile64(
    float* smem, int tb, int cb,
    const uint32_t* __restrict__ Ah, const uint32_t* __restrict__ Al,
    const uint32_t* __restrict__ Bh, float* __restrict__ Cout,
    const float* __restrict__ sflag, int ysel, bool b_prewait)
{
    const int tid = threadIdx.x, lane = tid & 31, wid = tid >> 5;
    const int wm = wid & 1, wn = wid >> 1;
    const int mb = tb >> 1, h = tb & 1;
    const uint32_t sbase = smem_u32(smem);
    uint32_t* smemU = (uint32_t*)smem;
    float acc[2][4][4];
#pragma unroll
    for (int i = 0; i < 2; i++)
#pragma unroll
        for (int j = 0; j < 4; j++)
#pragma unroll
            for (int q = 0; q < 4; q++) acc[i][j][q] = 0.0f;

    // smem (bytes): A buf0 [0,8192) | A buf1 [8192,16384) | B buf0 [16384,32768) | B buf1 [32768,49152)
    auto stageA = [&](int c, int buf) {
        const uint32_t* As = (((c >> 1) == 1) ? Al : Ah) + mb * FRAGH + (c & 1) * 4096;
        uint32_t da = sbase + buf * 8192;
#pragma unroll
        for (int i = 0; i < 2; i++) {
            int f = tid + 256 * i;
            int blk = f >> 5, lg = f & 31;
            cpasync16(da + f * 16, As + ((blk >> 2) * 8 + 4 * h + (blk & 3)) * 128 + lg * 4);
        }
    };
    auto stageB = [&](int c, int buf) {
        const uint32_t* Bs = Bh + cb * 24576 + c * 4096;
        uint32_t db = sbase + 16384 + buf * 16384;
#pragma unroll
        for (int i = 0; i < 4; i++) {
            int f = tid + 256 * i;
            cpasync16(db + f * 16, Bs + f * 4);
        }
    };

    if (b_prewait) {
        stageB(0, 0);
        PDL_WAIT();
        stageA(0, 0);
    } else {
        PDL_WAIT();
        stageB(0, 0);
        stageA(0, 0);
    }
    asm volatile("cp.async.commit_group;");
    for (int c = 0; c < 6; c++) {
        int buf = c & 1;
        if (c < 5) {
            stageA(c + 1, buf ^ 1);
            stageB(c + 1, buf ^ 1);
            asm volatile("cp.async.commit_group;");
            asm volatile("cp.async.wait_group 1;");
        } else {
            asm volatile("cp.async.wait_group 0;");
        }
        __syncthreads();
        const uint32_t* Ab = smemU + buf * 2048;
        const uint32_t* Bb = smemU + 4096 + buf * 4096;
#pragma unroll
        for (int ks = 0; ks < 4; ks++) {
            uint4 a[2];
            uint2 b[4];
#pragma unroll
            for (int mt = 0; mt < 2; mt++)
                a[mt] = *(const uint4*)(Ab + ((ks * 4 + wm * 2 + mt) * 32 + lane) * 4);
#pragma unroll
            for (int nt = 0; nt < 4; nt++)
                b[nt] = *(const uint2*)(Bb + ((ks * 16 + wn * 4 + nt) * 32 + lane) * 2);
#pragma unroll
            for (int mt = 0; mt < 2; mt++)
#pragma unroll
                for (int nt = 0; nt < 4; nt++)
                    mma_f16(acc[mt][nt], (const uint32_t*)&a[mt], (const uint32_t*)&b[nt]);
        }
        __syncthreads();
    }

    const int row0 = tb * 64, colofs = cb * 128;
#pragma unroll
    for (int mt = 0; mt < 2; mt++) {
        int rva = wm * 32 + mt * 16 + (lane >> 2);
        int rvb = rva + 8;
        int ga = row0 + rva, gb = row0 + rvb;
        const float *Pa = nullptr, *Pb = nullptr;
        bool ya = false, yb = false;
        if (MODE == 1) {
            if (ga < NN) Pa = g_rf[ga] ? g_P1 : g_P0;
            if (gb < NN) Pb = g_rf[gb] ? g_P1 : g_P0;
        } else {
            if (ga < NN) ya = (sflag[ga] > 0.5f) == (ysel != 0);
            if (gb < NN) yb = (sflag[gb] > 0.5f) == (ysel != 0);
        }
#pragma unroll
        for (int nt = 0; nt < 4; nt++) {
            int col = wn * 32 + nt * 8 + ((lane & 3) << 1);
            float c0 = acc[mt][nt][0], c1 = acc[mt][nt][1];
            float c2 = acc[mt][nt][2], c3 = acc[mt][nt][3];
            if (MODE == 0) {
                if (ga < NN) {
                    float2 v = {c0, c1};
                    *(float2*)(Cout + (size_t)ga * 256 + colofs + col) = v;
                    if (ya) *(float2*)(g_y + (size_t)ga * 256 + colofs + col) = v;
                }
                if (gb < NN) {
                    float2 v = {c2, c3};
                    *(float2*)(Cout + (size_t)gb * 256 + colofs + col) = v;
                    if (yb) *(float2*)(g_y + (size_t)gb * 256 + colofs + col) = v;
                }
            } else {
                if (ga < NN) {
                    float2 pv = *(const float2*)(Pa + (size_t)ga * 256 + colofs + col);
                    float2 v = {c0 + pv.x, c1 + pv.y};
                    *(float2*)(g_y + (size_t)ga * 256 + colofs + col) = v;
                }
                if (gb < NN) {
                    float2 pv = *(const float2*)(Pb + (size_t)gb * 256 + colofs + col);
                    float2 v = {c2 + pv.x, c3 + pv.y};
                    *(float2*)(g_y + (size_t)gb * 256 + colofs + col) = v;
                }
            }
        }
    }
}

// ---------------- GEMM2, 64-row tiles (PDL: B pre-wait, A post-wait) ----------------
__device__ __forceinline__ void gemm2_tile64(
    float* smem, int tb,
    const float* __restrict__ bias, const float* __restrict__ Wdec)
{
    const int tid = threadIdx.x, lane = tid & 31, wid = tid >> 5;
    const int wm = wid & 1, wn = wid >> 1;
    const int mb = tb >> 1, h = tb & 1;
    const uint32_t sbase = smem_u32(smem);
    uint32_t* smemU = (uint32_t*)smem;
    float acc[2][4][4];
#pragma unroll
    for (int i = 0; i < 2; i++)
#pragma unroll
        for (int j = 0; j < 4; j++)
#pragma unroll
            for (int q = 0; q < 4; q++) acc[i][j][q] = 0.0f;

    auto stageA = [&](int c, int buf) {
        const uint32_t* As = (((c >> 1) == 1) ? g_Glf : g_Ghf) + mb * FRAGH + (c & 1) * 4096;
        uint32_t da = sbase + buf * 8192;
#pragma unroll
        for (int i = 0; i < 2; i++) {
            int f = tid + 256 * i;
            int blk = f >> 5, lg = f & 31;
            cpasync16(da + f * 16, As + ((blk >> 2) * 8 + 4 * h + (blk & 3)) * 128 + lg * 4);
        }
    };
    auto stageB = [&](int c, int buf) {
        const uint32_t* Bs = g_B2h + c * 4096;
        uint32_t db = sbase + 16384 + buf * 16384;
#pragma unroll
        for (int i = 0; i < 4; i++) {
            int f = tid + 256 * i;
            cpasync16(db + f * 16, Bs + f * 4);
        }
    };

    stageB(0, 0);
    PDL_WAIT();
    stageA(0, 0);
    asm volatile("cp.async.commit_group;");
    for (int c = 0; c < 6; c++) {
        int buf = c & 1;
        if (c < 5) {
            stageA(c + 1, buf ^ 1);
            stageB(c + 1, buf ^ 1);
            asm volatile("cp.async.commit_group;");
            asm volatile("cp.async.wait_group 1;");
        } else {
            asm volatile("cp.async.wait_group 0;");
        }
        __syncthreads();
        const uint32_t* Ab = smemU + buf * 2048;
        const uint32_t* Bb = smemU + 4096 + buf * 4096;
#pragma unroll
        for (int ks = 0; ks < 4; ks++) {
            uint4 a[2];
            uint2 b[4];
#pragma unroll
            for (int mt = 0; mt < 2; mt++)
                a[mt] = *(const uint4*)(Ab + ((ks * 4 + wm * 2 + mt) * 32 + lane) * 4);
#pragma unroll
            for (int nt = 0; nt < 4; nt++)
                b[nt] = *(const uint2*)(Bb + ((ks * 16 + wn * 4 + nt) * 32 + lane) * 2);
#pragma unroll
            for (int mt = 0; mt < 2; mt++)
#pragma unroll
                for (int nt = 0; nt < 4; nt++)
                    mma_f16(acc[mt][nt], (const uint32_t*)&a[mt], (const uint32_t*)&b[nt]);
        }
        __syncthreads();
    }

    const int row0 = mb * 128 + h * 64;
    float s1r[4], s2r[4];
#pragma unroll
    for (int i = 0; i < 4; i++) { s1r[i] = 0.0f; s2r[i] = 0.0f; }

#pragma unroll
    for (int mt = 0; mt < 2; mt++) {
        int rva = wm * 32 + mt * 16 + (lane >> 2);
        int rvb = rva + 8;
        int ga = row0 + rva, gb = row0 + rvb;
#pragma unroll
        for (int nt = 0; nt < 4; nt++) {
            int col = wn * 32 + nt * 8 + ((lane & 3) << 1);
            float c0 = acc[mt][nt][0], c1 = acc[mt][nt][1];
            float c2 = acc[mt][nt][2], c3 = acc[mt][nt][3];
            float b0 = bias[col], b1 = bias[col + 1];
            float w10 = Wdec[col], w11 = Wdec[col + 1];
            float w20 = Wdec[128 + col], w21 = Wdec[128 + col + 1];
            float v0 = fmaxf(c0 + b0, 0.0f), v1 = fmaxf(c1 + b1, 0.0f);
            float v2 = fmaxf(c2 + b0, 0.0f), v3 = fmaxf(c3 + b1, 0.0f);
            s1r[mt * 2 + 0] += v0 * w10 + v1 * w11;
            s2r[mt * 2 + 0] += v0 * w20 + v1 * w21;
            s1r[mt * 2 + 1] += v2 * w10 + v3 * w11;
            s2r[mt * 2 + 1] += v2 * w20 + v3 * w21;
            if (ga < NN) {
                int i0 = mb * FRAGH + fidxh(h * 64 + rva, col);
                g_Ahf[i0] = pk2h(v0, v1);
                g_Alf[i0] = pk2h(v0 - hi16(v0), v1 - hi16(v1));
            }
            if (gb < NN) {
                int i0 = mb * FRAGH + fidxh(h * 64 + rvb, col);
                g_Ahf[i0] = pk2h(v2, v3);
                g_Alf[i0] = pk2h(v2 - hi16(v2), v3 - hi16(v3));
            }
        }
    }
    {
        float* red = smem;
        int t3 = lane & 3;
#pragma unroll
        for (int mt = 0; mt < 2; mt++)
#pragma unroll
            for (int hf = 0; hf < 2; hf++) {
                int rl = wm * 32 + mt * 16 + (lane >> 2) + hf * 8;
                red[rl * 16 + wn * 4 + t3] = s1r[mt * 2 + hf];
                red[1024 + rl * 16 + wn * 4 + t3] = s2r[mt * 2 + hf];
            }
        __syncthreads();
        if (tid < 64) {
            int ga = row0 + tid;
            if (ga < NN) {
                float a = 0.0f, b = 0.0f;
#pragma unroll
                for (int q = 0; q < 16; q++) { a += red[tid * 16 + q]; b += red[1024 + tid * 16 + q]; }
                g_a1[ga] = a;
                g_a2[ga] = b;
            }
        }
        __syncthreads();
    }
}

// setup: blocks [0, 4*MBK) -> P0 (A=z0-frag), rest -> P1 (A=z1-frag); epilogue inits y by s-select
// B tables come from k_fused -> must be post-wait (b_prewait=false)
__global__ __launch_bounds__(256) void k_setupgemm(const float* __restrict__ s) {
    PDL_TRIGGER();
    extern __shared__ float smem[];
    int b = blockIdx.x;
    if (b < 4 * MBK)
        gemm_tile64<0>(smem, b >> 1, b & 1, g_Ahf, g_Alf, g_BPh, g_P0, s, 0, false);
    else {
        b -= 4 * MBK;
        gemm_tile64<0>(smem, b >> 1, b & 1, g_Ghf, g_Glf, g_BPh, g_P1, s, 1, false);
    }
}
__global__ __launch_bounds__(256) void k_gemm1() {
    PDL_TRIGGER();
    extern __shared__ float smem[];
    gemm_tile64<1>(smem, blockIdx.x, blockIdx.y, g_Ahf, g_Alf, g_B1h, nullptr, nullptr, 0, true);
}
__global__ __launch_bounds__(256) void k_gemm2(const float* __restrict__ bout,
                                               const float* __restrict__ Wdec) {
    PDL_TRIGGER();
    extern __shared__ float smem[];
    gemm2_tile64(smem, blockIdx.x, bout, Wdec);
}

// ---------------- iteration kernels ----------------
// 2 warps per node: segment max over half the channels; relu(max+y2+b); frag write; rf zero
__global__ void k_segmax(const float* __restrict__ bmsg) {
    PDL_TRIGGER();
    int u = (blockIdx.x * blockDim.x + threadIdx.x) >> 5;
    int lane = threadIdx.x & 31;
    if (u >= NN * 2) return;
    int w = u >> 1, hf = u & 1;
    int beg = g_indptr[w], end = g_indptr[w + 1];
    int c0 = hf * 64 + lane * 2;
    PDL_WAIT();   // g_y (and rf-zero safety vs gemm1 epilogue) gated here
    float m0 = -INFINITY, m1 = -INFINITY;
    int j = beg;
    for (; j + 3 < end; j += 4) {
        int s0 = g_csr_src[j], s1 = g_csr_src[j + 1];
        int s2 = g_csr_src[j + 2], s3 = g_csr_src[j + 3];
        float2 v0 = *(const float2*)(g_y + (size_t)s0 * 256 + c0);
        float2 v1 = *(const float2*)(g_y + (size_t)s1 * 256 + c0);
        float2 v2 = *(const float2*)(g_y + (size_t)s2 * 256 + c0);
        float2 v3 = *(const float2*)(g_y + (size_t)s3 * 256 + c0);
        m0 = fmaxf(fmaxf(m0, fmaxf(v0.x, v1.x)), fmaxf(v2.x, v3.x));
        m1 = fmaxf(fmaxf(m1, fmaxf(v0.y, v1.y)), fmaxf(v2.y, v3.y));
    }
    for (; j < end; j++) {
        int s0 = g_csr_src[j];
        float2 v0 = *(const float2*)(g_y + (size_t)s0 * 256 + c0);
        m0 = fmaxf(m0, v0.x);
        m1 = fmaxf(m1, v0.y);
    }
    float o0, o1;
    if (end > beg) {
        float2 y2 = *(const float2*)(g_y + (size_t)w * 256 + 128 + c0);
        float2 b = *(const float2*)(bmsg + c0);
        o0 = fmaxf(m0 + y2.x + b.x, 0.0f);
        o1 = fmaxf(m1 + y2.y + b.y, 0.0f);
    } else { o0 = 0.0f; o1 = 0.0f; }
    int i0 = (w >> 7) * FRAGH + fidxh(w & 127, c0);
    g_Ghf[i0] = pk2h(o0, o1);
    g_Glf[i0] = pk2h(o0 - hi16(o0), o1 - hi16(o1));
    if (hf == 0 && lane == 0) g_rf[w] = 0;
}

// 2 edges per thread, vectorized; edge indices pre-loaded before PDL wait
__global__ void k_alpha(const int* __restrict__ ei, const float* __restrict__ bdec,
                        float* __restrict__ out, int it) {
    PDL_TRIGGER();
    int e = (blockIdx.x * blockDim.x + threadIdx.x) * 2;
    if (e >= EE) return;
    int2 sv = *(const int2*)(ei + e);
    int2 dv = *(const int2*)(ei + EE + e);
    float bd = bdec[0];
    PDL_WAIT();   // a1/a2 from gemm2 gated here
    float t0 = g_a1[sv.x] + g_a2[dv.x] + bd;
    float t1 = g_a1[sv.y] + g_a2[dv.y] + bd;
    float al0 = sigmoidf_fast(t0);
    float al1 = sigmoidf_fast(t1);
    float2 o = {al0, al1};
    *(float2*)(out + (size_t)it * EE + e) = o;
    if (al0 >= 0.4f) { g_rf[sv.x] = 1; g_rf[dv.x] = 1; }
    if (al1 >= 0.4f) { g_rf[sv.y] = 1; g_rf[dv.y] = 1; }
}

__global__ void k_final(const float* __restrict__ bdec, float* __restrict__ out) {
    int w = (blockIdx.x * blockDim.x + threadIdx.x) >> 5;
    int lane = threadIdx.x & 31;
    if (w >= NN) return;
    int beg = g_indptr[w], end = g_indptr[w + 1];
    float bd = bdec[0];
    PDL_WAIT();
    if (lane == 0) out[(size_t)10 * EE + w] = g_rf[w] ? 1.0f : 0.0f;
    float a2v = g_a2[w];
    float ba = -1.0f;
    int beid = 0x7FFFFFFF, bsrc = w;
    for (int j = beg + lane; j < end; j += 32) {
        int sv = g_csr_src[j], eid = g_csr_eid[j];
        float t = g_a1[sv] + a2v + bd;
        float al = sigmoidf_fast(t);
        if (al > ba || (al == ba && eid < beid)) { ba = al; beid = eid; bsrc = sv; }
    }
#pragma unroll
    for (int o = 16; o; o >>= 1) {
        float oa = __shfl_xor_sync(0xFFFFFFFFu, ba, o);
        int oe = __shfl_xor_sync(0xFFFFFFFFu, beid, o);
        int os = __shfl_xor_sync(0xFFFFFFFFu, bsrc, o);
        if (oa > ba || (oa == ba && oe < beid)) { ba = oa; beid = oe; bsrc = os; }
    }
    if (lane == 0) out[(size_t)10 * EE + NN + w] = (float)((end > beg) ? bsrc : w);
}

// ---------------- host ----------------
static void launch_pdl(const void* func, dim3 grid, dim3 block, size_t smem, void** args) {
    cudaLaunchConfig_t cfg = {};
    cfg.gridDim = grid;
    cfg.blockDim = block;
    cfg.dynamicSmemBytes = smem;
    cfg.stream = 0;
    cudaLaunchAttribute attr;
    attr.id = cudaLaunchAttributeProgrammaticStreamSerialization;
    attr.val.programmaticStreamSerializationAllowed = 1;
    cfg.attrs = &attr;
    cfg.numAttrs = 1;
    cudaLaunchKernelExC(&cfg, func, args);
}

extern "C" void kernel_launch(void* const* d_in, const int* in_sizes, int n_in,
                              void* d_out, int out_size) {
    const float* pos  = (const float*)d_in[0];
    const float* s    = (const float*)d_in[1];
    const int*   ei   = (const int*)d_in[2];
    const float* Wenc = (const float*)d_in[3];
    const float* benc = (const float*)d_in[4];
    const float* W1   = (const float*)d_in[5];
    const float* W2   = (const float*)d_in[6];
    const float* bmsg = (const float*)d_in[7];
    const float* Wout = (const float*)d_in[8];
    const float* bout = (const float*)d_in[9];
    const float* Wdec = (const float*)d_in[10];
    const float* bdec = (const float*)d_in[11];
    float* out = (float*)d_out;

    const int SMEM2 = 49152;
    cudaFuncSetAttribute(k_setupgemm, cudaFuncAttributeMaxDynamicSharedMemorySize, SMEM2);
    cudaFuncSetAttribute(k_gemm1, cudaFuncAttributeMaxDynamicSharedMemorySize, SMEM2);
    cudaFuncSetAttribute(k_gemm2, cudaFuncAttributeMaxDynamicSharedMemorySize, SMEM2);

    const int TB = 256;
    k_init<<<(NN + TB - 1) / TB, TB>>>();
    k_hist<<<(EE + TB - 1) / TB, TB>>>(ei);
    k_scan<<<1, 1024>>>();
    k_fused<<<1024, TB>>>(ei, W1, W2, Wout, pos, Wenc, benc);
    {
        void* args[] = {(void*)&s};
        launch_pdl((const void*)k_setupgemm, dim3(8 * MBK), dim3(TB), SMEM2, args);
    }

    for (int it = 0; it < ITERS; it++) {
        if (it > 0)
            launch_pdl((const void*)k_gemm1, dim3(2 * MBK, 2), dim3(TB), SMEM2, nullptr);
        {
            void* args[] = {(void*)&bmsg};
            launch_pdl((const void*)k_segmax, dim3((NN * 2 + 7) / 8), dim3(TB), 0, args);
        }
        {
            void* args[] = {(void*)&bout, (void*)&Wdec};
            launch_pdl((const void*)k_gemm2, dim3(2 * MBK), dim3(TB), SMEM2, args);
        }
        {
            int itv = it;
            void* args[] = {(void*)&ei, (void*)&bdec, (void*)&out, (void*)&itv};
            launch_pdl((const void*)k_alpha, dim3((EE / 2 + TB - 1) / TB), dim3(TB), 0, args);
        }
    }
    {
        void* args[] = {(void*)&bdec, (void*)&out};
        launch_pdl((const void*)k_final, dim3((NN + 7) / 8), dim3(TB), 0, args);
    }
}

// round 17
// speedup vs baseline: 1.0926x; 1.0345x over previous
#include <cuda_runtime.h>
#include <cuda_fp16.h>
#include <math.h>
#include <stdint.h>

#define NN 20000
#define EE 320000
#define ITERS 10
#define MBK 157
#define FRAGH 8192   // u32 words per 128x128 fp16 A-fragment block

#define PDL_TRIGGER() asm volatile("griddepcontrol.launch_dependents;")
#define PDL_WAIT()    asm volatile("griddepcontrol.wait;")

// ---------------- device scratch ----------------
__device__ float g_P0[NN * 256], g_P1[NN * 256], g_y[NN * 256];
__device__ __align__(16) uint32_t g_Ahf[MBK * FRAGH], g_Alf[MBK * FRAGH];  // h hi/lo frag (z0 during setup)
__device__ __align__(16) uint32_t g_Ghf[MBK * FRAGH], g_Glf[MBK * FRAGH];  // agg hi/lo frag (z1 during setup)
__device__ float g_a1[NN], g_a2[NN];
__device__ int   g_rf[NN];           // reach flag (any incident alpha >= 0.4)
__device__ int   g_deg[NN], g_indptr[NN + 1], g_cursor[NN];
__device__ int   g_csr_src[EE], g_csr_eid[EE];
__device__ __align__(16) uint32_t g_B1h[2 * 24576];  // h-rows of [W1|W2], frag layout (hi,hi,lo)
__device__ __align__(16) uint32_t g_BPh[2 * 24576];  // z-rows of [W1|W2]
__device__ __align__(16) uint32_t g_B2h[24576];      // Wout

// ---------------- helpers ----------------
__device__ __forceinline__ uint32_t smem_u32(const void* p) {
    uint32_t a;
    asm("{ .reg .u64 t; cvta.to.shared.u64 t, %1; cvt.u32.u64 %0, t; }" : "=r"(a) : "l"(p));
    return a;
}
__device__ __forceinline__ void cpasync16(uint32_t dst, const void* src) {
    asm volatile("cp.async.cg.shared.global [%0], [%1], 16;" :: "r"(dst), "l"(src));
}
__device__ __forceinline__ uint32_t pk2h(float a, float b) {
    __half2 h = __floats2half2_rn(a, b);
    return *(uint32_t*)&h;
}
__device__ __forceinline__ float hi16(float v) { return __half2float(__float2half_rn(v)); }
__device__ __forceinline__ void mma_f16(float* c, const uint32_t* a, const uint32_t* b) {
    asm volatile(
        "mma.sync.aligned.m16n8k16.row.col.f32.f16.f16.f32 "
        "{%0,%1,%2,%3}, {%4,%5,%6,%7}, {%8,%9}, {%0,%1,%2,%3};"
        : "+f"(c[0]), "+f"(c[1]), "+f"(c[2]), "+f"(c[3])
        : "r"(a[0]), "r"(a[1]), "r"(a[2]), "r"(a[3]), "r"(b[0]), "r"(b[1]));
}
__device__ __forceinline__ float sigmoidf_fast(float t) {
    return 1.0f / (1.0f + __expf(-t));
}
// word index of (row rv in [0,128), even col cc in [0,128)) inside one A-frag block
__device__ __forceinline__ int fidxh(int rv, int cc) {
    int ks = cc >> 4, kk = cc & 15, mt = rv >> 4, r = rv & 15;
    int slot = (r >> 3) + ((kk >> 3) << 1);
    int lane = ((r & 7) << 2) | ((kk & 7) >> 1);
    return ((ks * 8 + mt) * 32 + lane) * 4 + slot;
}

// ---------------- setup kernels ----------------
__global__ void k_init() {
    int t = blockIdx.x * blockDim.x + threadIdx.x;
    if (t < NN) { g_deg[t] = 0; g_rf[t] = 0; }
}
__global__ void k_hist(const int* __restrict__ ei) {
    int e = blockIdx.x * blockDim.x + threadIdx.x;
    if (e < EE) atomicAdd(&g_deg[ei[EE + e]], 1);
}
__global__ void k_scan() {
    __shared__ int sh[1024];
    int t = threadIdx.x;
    const int CH = 20;
    int base = t * CH, s = 0;
    for (int i = 0; i < CH; i++) { int idx = base + i; if (idx < NN) s += g_deg[idx]; }
    sh[t] = s;
    __syncthreads();
    for (int o = 1; o < 1024; o <<= 1) {
        int v = (t >= o) ? sh[t - o] : 0;
        __syncthreads();
        sh[t] += v;
        __syncthreads();
    }
    int run = (t == 0) ? 0 : sh[t - 1];
    for (int i = 0; i < CH; i++) {
        int idx = base + i;
        if (idx < NN) { g_indptr[idx] = run; g_cursor[idx] = run; run += g_deg[idx]; }
    }
    if (t == 1023) g_indptr[NN] = sh[1023];
}

// fused: CSR scatter + fp16 B-table packing + z0/z1 frag prep
__global__ void k_fused(const int* __restrict__ ei,
                        const float* __restrict__ W1, const float* __restrict__ W2,
                        const float* __restrict__ Wout,
                        const float* __restrict__ pos, const float* __restrict__ Wenc,
                        const float* __restrict__ benc) {
    int t0 = blockIdx.x * blockDim.x + threadIdx.x;
    int gs = gridDim.x * blockDim.x;
    for (int e = t0; e < EE; e += gs) {
        int d = ei[EE + e];
        int slot = atomicAdd(&g_cursor[d], 1);
        g_csr_src[slot] = ei[e];
        g_csr_eid[slot] = e;
    }
    for (int t = t0; t < 122880; t += gs) {
        int which, w;
        if (t < 49152) { which = 0; w = t; }
        else if (t < 98304) { which = 1; w = t - 49152; }
        else { which = 2; w = t - 98304; }
        int cb = w / 24576;
        int rem = w % 24576;
        int gks = rem >> 10;
        int r = rem & 1023;
        int nt = r >> 6;
        int r2 = r & 63;
        int lane = r2 >> 1, slot = r2 & 1;
        int n = cb * 128 + nt * 8 + (lane >> 2);
        int k0 = (gks & 7) * 16 + (lane & 3) * 2 + slot * 8;
        int term = gks >> 3;   // 0,1 = hi ; 2 = lo
        float v0, v1;
        if (which == 0) {
            v0 = (n < 128) ? W1[(128 + k0) * 128 + n] : W2[(128 + k0) * 128 + (n - 128)];
            v1 = (n < 128) ? W1[(129 + k0) * 128 + n] : W2[(129 + k0) * 128 + (n - 128)];
        } else if (which == 1) {
            v0 = (n < 128) ? W1[k0 * 128 + n] : W2[k0 * 128 + (n - 128)];
            v1 = (n < 128) ? W1[(k0 + 1) * 128 + n] : W2[(k0 + 1) * 128 + (n - 128)];
        } else {
            v0 = Wout[k0 * 128 + n];
            v1 = Wout[(k0 + 1) * 128 + n];
        }
        uint32_t word;
        if (term < 2) word = pk2h(v0, v1);
        else          word = pk2h(v0 - hi16(v0), v1 - hi16(v1));
        if (which == 0) g_B1h[w] = word;
        else if (which == 1) g_BPh[w] = word;
        else g_B2h[w] = word;
    }
    for (int t = t0; t < NN * 32; t += gs) {
        int v = t >> 5, c0 = (t & 31) << 2;
        float p = pos[v];
        float4 w0 = *(const float4*)(Wenc + c0);
        float4 w1 = *(const float4*)(Wenc + 128 + c0);
        float4 b = *(const float4*)(benc + c0);
        int base = (v >> 7) * FRAGH;
        int rv = v & 127;
        int i0 = base + fidxh(rv, c0);
        int i1 = base + fidxh(rv, c0 + 2);
#pragma unroll
        for (int rr = 0; rr < 2; rr++) {
            float rf = (float)rr;
            float z0 = fmaxf(fmaf(p, w0.x, fmaf(rf, w1.x, b.x)), 0.0f);
            float z1 = fmaxf(fmaf(p, w0.y, fmaf(rf, w1.y, b.y)), 0.0f);
            float z2 = fmaxf(fmaf(p, w0.z, fmaf(rf, w1.z, b.z)), 0.0f);
            float z3 = fmaxf(fmaf(p, w0.w, fmaf(rf, w1.w, b.w)), 0.0f);
            uint32_t* dh = rr ? g_Ghf : g_Ahf;
            uint32_t* dl = rr ? g_Glf : g_Alf;
            dh[i0] = pk2h(z0, z1);
            dl[i0] = pk2h(z0 - hi16(z0), z1 - hi16(z1));
            dh[i1] = pk2h(z2, z3);
            dl[i1] = pk2h(z2 - hi16(z2), z3 - hi16(z3));
        }
    }
}

// ---------------- 64-row fp16-split GEMM tile (64x128, K_ext=384, 256 thr, 48KB smem dbuf) ----------------
// WAITMODE 0: PDL_WAIT before any staging (setup; B tables not yet ready)
// WAITMODE 2: full mainloop pre-wait; PDL_WAIT only before epilogue (gemm1: A frags
//             are safe because alpha triggers post-wait => gemm2 complete at launch)
// MODE 0: raw fp32 -> Cout + conditional y init by s-select
// MODE 1: acc + P_sel(g_rf) -> g_y
template <int MODE, int WAITMODE>
__device__ __forceinline__ void gemm_tile64(
    float* smem, int tb, int cb,
    const uint32_t* __restrict__ Ah, const uint32_t* __restrict__ Al,
    const uint32_t* __restrict__ Bh, float* __restrict__ Cout,
    const float* __restrict__ sflag, int ysel)
{
    const int tid = threadIdx.x, lane = tid & 31, wid = tid >> 5;
    const int wm = wid & 1, wn = wid >> 1;
    const int mb = tb >> 1, h = tb & 1;
    const uint32_t sbase = smem_u32(smem);
    uint32_t* smemU = (uint32_t*)smem;
    float acc[2][4][4];
#pragma unroll
    for (int i = 0; i < 2; i++)
#pragma unroll
        for (int j = 0; j < 4; j++)
#pragma unroll
            for (int q = 0; q < 4; q++) acc[i][j][q] = 0.0f;

    // smem (bytes): A buf0 [0,8192) | A buf1 [8192,16384) | B buf0 [16384,32768) | B buf1 [32768,49152)
    auto stageA = [&](int c, int buf) {
        const uint32_t* As = (((c >> 1) == 1) ? Al : Ah) + mb * FRAGH + (c & 1) * 4096;
        uint32_t da = sbase + buf * 8192;
#pragma unroll
        for (int i = 0; i < 2; i++) {
            int f = tid + 256 * i;
            int blk = f >> 5, lg = f & 31;
            cpasync16(da + f * 16, As + ((blk >> 2) * 8 + 4 * h + (blk & 3)) * 128 + lg * 4);
        }
    };
    auto stageB = [&](int c, int buf) {
        const uint32_t* Bs = Bh + cb * 24576 + c * 4096;
        uint32_t db = sbase + 16384 + buf * 16384;
#pragma unroll
        for (int i = 0; i < 4; i++) {
            int f = tid + 256 * i;
            cpasync16(db + f * 16, Bs + f * 4);
        }
    };

    if (WAITMODE == 0) PDL_WAIT();
    stageB(0, 0);
    stageA(0, 0);
    asm volatile("cp.async.commit_group;");
    for (int c = 0; c < 6; c++) {
        int buf = c & 1;
        if (c < 5) {
            stageA(c + 1, buf ^ 1);
            stageB(c + 1, buf ^ 1);
            asm volatile("cp.async.commit_group;");
            asm volatile("cp.async.wait_group 1;");
        } else {
            asm volatile("cp.async.wait_group 0;");
        }
        __syncthreads();
        const uint32_t* Ab = smemU + buf * 2048;
        const uint32_t* Bb = smemU + 4096 + buf * 4096;
#pragma unroll
        for (int ks = 0; ks < 4; ks++) {
            uint4 a[2];
            uint2 b[4];
#pragma unroll
            for (int mt = 0; mt < 2; mt++)
                a[mt] = *(const uint4*)(Ab + ((ks * 4 + wm * 2 + mt) * 32 + lane) * 4);
#pragma unroll
            for (int nt = 0; nt < 4; nt++)
                b[nt] = *(const uint2*)(Bb + ((ks * 16 + wn * 4 + nt) * 32 + lane) * 2);
#pragma unroll
            for (int mt = 0; mt < 2; mt++)
#pragma unroll
                for (int nt = 0; nt < 4; nt++)
                    mma_f16(acc[mt][nt], (const uint32_t*)&a[mt], (const uint32_t*)&b[nt]);
        }
        __syncthreads();
    }

    if (WAITMODE == 2) PDL_WAIT();   // gate g_rf read / g_y write on alpha completion
    const int row0 = tb * 64, colofs = cb * 128;
#pragma unroll
    for (int mt = 0; mt < 2; mt++) {
        int rva = wm * 32 + mt * 16 + (lane >> 2);
        int rvb = rva + 8;
        int ga = row0 + rva, gb = row0 + rvb;
        const float *Pa = nullptr, *Pb = nullptr;
        bool ya = false, yb = false;
        if (MODE == 1) {
            if (ga < NN) Pa = g_rf[ga] ? g_P1 : g_P0;
            if (gb < NN) Pb = g_rf[gb] ? g_P1 : g_P0;
        } else {
            if (ga < NN) ya = (sflag[ga] > 0.5f) == (ysel != 0);
            if (gb < NN) yb = (sflag[gb] > 0.5f) == (ysel != 0);
        }
#pragma unroll
        for (int nt = 0; nt < 4; nt++) {
            int col = wn * 32 + nt * 8 + ((lane & 3) << 1);
            float c0 = acc[mt][nt][0], c1 = acc[mt][nt][1];
            float c2 = acc[mt][nt][2], c3 = acc[mt][nt][3];
            if (MODE == 0) {
                if (ga < NN) {
                    float2 v = {c0, c1};
                    *(float2*)(Cout + (size_t)ga * 256 + colofs + col) = v;
                    if (ya) *(float2*)(g_y + (size_t)ga * 256 + colofs + col) = v;
                }
                if (gb < NN) {
                    float2 v = {c2, c3};
                    *(float2*)(Cout + (size_t)gb * 256 + colofs + col) = v;
                    if (yb) *(float2*)(g_y + (size_t)gb * 256 + colofs + col) = v;
                }
            } else {
                if (ga < NN) {
                    float2 pv = *(const float2*)(Pa + (size_t)ga * 256 + colofs + col);
                    float2 v = {c0 + pv.x, c1 + pv.y};
                    *(float2*)(g_y + (size_t)ga * 256 + colofs + col) = v;
                }
                if (gb < NN) {
                    float2 pv = *(const float2*)(Pb + (size_t)gb * 256 + colofs + col);
                    float2 v = {c2 + pv.x, c3 + pv.y};
                    *(float2*)(g_y + (size_t)gb * 256 + colofs + col) = v;
                }
            }
        }
    }
}

// ---------------- GEMM2, 64-row tiles (PDL: B pre-wait, A post-wait) ----------------
__device__ __forceinline__ void gemm2_tile64(
    float* smem, int tb,
    const float* __restrict__ bias, const float* __restrict__ Wdec)
{
    const int tid = threadIdx.x, lane = tid & 31, wid = tid >> 5;
    const int wm = wid & 1, wn = wid >> 1;
    const int mb = tb >> 1, h = tb & 1;
    const uint32_t sbase = smem_u32(smem);
    uint32_t* smemU = (uint32_t*)smem;
    float acc[2][4][4];
#pragma unroll
    for (int i = 0; i < 2; i++)
#pragma unroll
        for (int j = 0; j < 4; j++)
#pragma unroll
            for (int q = 0; q < 4; q++) acc[i][j][q] = 0.0f;

    auto stageA = [&](int c, int buf) {
        const uint32_t* As = (((c >> 1) == 1) ? g_Glf : g_Ghf) + mb * FRAGH + (c & 1) * 4096;
        uint32_t da = sbase + buf * 8192;
#pragma unroll
        for (int i = 0; i < 2; i++) {
            int f = tid + 256 * i;
            int blk = f >> 5, lg = f & 31;
            cpasync16(da + f * 16, As + ((blk >> 2) * 8 + 4 * h + (blk & 3)) * 128 + lg * 4);
        }
    };
    auto stageB = [&](int c, int buf) {
        const uint32_t* Bs = g_B2h + c * 4096;
        uint32_t db = sbase + 16384 + buf * 16384;
#pragma unroll
        for (int i = 0; i < 4; i++) {
            int f = tid + 256 * i;
            cpasync16(db + f * 16, Bs + f * 4);
        }
    };

    stageB(0, 0);
    PDL_WAIT();
    stageA(0, 0);
    asm volatile("cp.async.commit_group;");
    for (int c = 0; c < 6; c++) {
        int buf = c & 1;
        if (c < 5) {
            stageA(c + 1, buf ^ 1);
            stageB(c + 1, buf ^ 1);
            asm volatile("cp.async.commit_group;");
            asm volatile("cp.async.wait_group 1;");
        } else {
            asm volatile("cp.async.wait_group 0;");
        }
        __syncthreads();
        const uint32_t* Ab = smemU + buf * 2048;
        const uint32_t* Bb = smemU + 4096 + buf * 4096;
#pragma unroll
        for (int ks = 0; ks < 4; ks++) {
            uint4 a[2];
            uint2 b[4];
#pragma unroll
            for (int mt = 0; mt < 2; mt++)
                a[mt] = *(const uint4*)(Ab + ((ks * 4 + wm * 2 + mt) * 32 + lane) * 4);
#pragma unroll
            for (int nt = 0; nt < 4; nt++)
                b[nt] = *(const uint2*)(Bb + ((ks * 16 + wn * 4 + nt) * 32 + lane) * 2);
#pragma unroll
            for (int mt = 0; mt < 2; mt++)
#pragma unroll
                for (int nt = 0; nt < 4; nt++)
                    mma_f16(acc[mt][nt], (const uint32_t*)&a[mt], (const uint32_t*)&b[nt]);
        }
        __syncthreads();
    }

    const int row0 = mb * 128 + h * 64;
    float s1r[4], s2r[4];
#pragma unroll
    for (int i = 0; i < 4; i++) { s1r[i] = 0.0f; s2r[i] = 0.0f; }

#pragma unroll
    for (int mt = 0; mt < 2; mt++) {
        int rva = wm * 32 + mt * 16 + (lane >> 2);
        int rvb = rva + 8;
        int ga = row0 + rva, gb = row0 + rvb;
#pragma unroll
        for (int nt = 0; nt < 4; nt++) {
            int col = wn * 32 + nt * 8 + ((lane & 3) << 1);
            float c0 = acc[mt][nt][0], c1 = acc[mt][nt][1];
            float c2 = acc[mt][nt][2], c3 = acc[mt][nt][3];
            float b0 = bias[col], b1 = bias[col + 1];
            float w10 = Wdec[col], w11 = Wdec[col + 1];
            float w20 = Wdec[128 + col], w21 = Wdec[128 + col + 1];
            float v0 = fmaxf(c0 + b0, 0.0f), v1 = fmaxf(c1 + b1, 0.0f);
            float v2 = fmaxf(c2 + b0, 0.0f), v3 = fmaxf(c3 + b1, 0.0f);
            s1r[mt * 2 + 0] += v0 * w10 + v1 * w11;
            s2r[mt * 2 + 0] += v0 * w20 + v1 * w21;
            s1r[mt * 2 + 1] += v2 * w10 + v3 * w11;
            s2r[mt * 2 + 1] += v2 * w20 + v3 * w21;
            if (ga < NN) {
                int i0 = mb * FRAGH + fidxh(h * 64 + rva, col);
                g_Ahf[i0] = pk2h(v0, v1);
                g_Alf[i0] = pk2h(v0 - hi16(v0), v1 - hi16(v1));
            }
            if (gb < NN) {
                int i0 = mb * FRAGH + fidxh(h * 64 + rvb, col);
                g_Ahf[i0] = pk2h(v2, v3);
                g_Alf[i0] = pk2h(v2 - hi16(v2), v3 - hi16(v3));
            }
        }
    }
    {
        float* red = smem;
        int t3 = lane & 3;
#pragma unroll
        for (int mt = 0; mt < 2; mt++)
#pragma unroll
            for (int hf = 0; hf < 2; hf++) {
                int rl = wm * 32 + mt * 16 + (lane >> 2) + hf * 8;
                red[rl * 16 + wn * 4 + t3] = s1r[mt * 2 + hf];
                red[1024 + rl * 16 + wn * 4 + t3] = s2r[mt * 2 + hf];
            }
        __syncthreads();
        if (tid < 64) {
            int ga = row0 + tid;
            if (ga < NN) {
                float a = 0.0f, b = 0.0f;
#pragma unroll
                for (int q = 0; q < 16; q++) { a += red[tid * 16 + q]; b += red[1024 + tid * 16 + q]; }
                g_a1[ga] = a;
                g_a2[ga] = b;
            }
        }
        __syncthreads();
    }
}

// setup: blocks [0, 4*MBK) -> P0 (A=z0-frag), rest -> P1 (A=z1-frag); epilogue inits y by s-select
__global__ __launch_bounds__(256) void k_setupgemm(const float* __restrict__ s) {
    PDL_TRIGGER();
    extern __shared__ float smem[];
    int b = blockIdx.x;
    if (b < 4 * MBK)
        gemm_tile64<0, 0>(smem, b >> 1, b & 1, g_Ahf, g_Alf, g_BPh, g_P0, s, 0);
    else {
        b -= 4 * MBK;
        gemm_tile64<0, 0>(smem, b >> 1, b & 1, g_Ghf, g_Glf, g_BPh, g_P1, s, 1);
    }
}
// gemm1: full mainloop pre-wait (A frags safe: alpha triggers post-wait => gemm2 done at launch)
__global__ __launch_bounds__(256) void k_gemm1() {
    PDL_TRIGGER();
    extern __shared__ float smem[];
    gemm_tile64<1, 2>(smem, blockIdx.x, blockIdx.y, g_Ahf, g_Alf, g_B1h, nullptr, nullptr, 0);
}
__global__ __launch_bounds__(256) void k_gemm2(const float* __restrict__ bout,
                                               const float* __restrict__ Wdec) {
    PDL_TRIGGER();
    extern __shared__ float smem[];
    gemm2_tile64(smem, blockIdx.x, bout, Wdec);
}

// ---------------- iteration kernels ----------------
// 2 warps per node: segment max over half the channels; relu(max+y2+b); frag write; rf zero
__global__ void k_segmax(const float* __restrict__ bmsg) {
    PDL_TRIGGER();
    int u = (blockIdx.x * blockDim.x + threadIdx.x) >> 5;
    int lane = threadIdx.x & 31;
    if (u >= NN * 2) return;
    int w = u >> 1, hf = u & 1;
    int beg = g_indptr[w], end = g_indptr[w + 1];
    int c0 = hf * 64 + lane * 2;
    PDL_WAIT();   // g_y from gemm1 gated here
    float m0 = -INFINITY, m1 = -INFINITY;
    int j = beg;
    for (; j + 3 < end; j += 4) {
        int s0 = g_csr_src[j], s1 = g_csr_src[j + 1];
        int s2 = g_csr_src[j + 2], s3 = g_csr_src[j + 3];
        float2 v0 = *(const float2*)(g_y + (size_t)s0 * 256 + c0);
        float2 v1 = *(const float2*)(g_y + (size_t)s1 * 256 + c0);
        float2 v2 = *(const float2*)(g_y + (size_t)s2 * 256 + c0);
        float2 v3 = *(const float2*)(g_y + (size_t)s3 * 256 + c0);
        m0 = fmaxf(fmaxf(m0, fmaxf(v0.x, v1.x)), fmaxf(v2.x, v3.x));
        m1 = fmaxf(fmaxf(m1, fmaxf(v0.y, v1.y)), fmaxf(v2.y, v3.y));
    }
    for (; j < end; j++) {
        int s0 = g_csr_src[j];
        float2 v0 = *(const float2*)(g_y + (size_t)s0 * 256 + c0);
        m0 = fmaxf(m0, v0.x);
        m1 = fmaxf(m1, v0.y);
    }
    float o0, o1;
    if (end > beg) {
        float2 y2 = *(const float2*)(g_y + (size_t)w * 256 + 128 + c0);
        float2 b = *(const float2*)(bmsg + c0);
        o0 = fmaxf(m0 + y2.x + b.x, 0.0f);
        o1 = fmaxf(m1 + y2.y + b.y, 0.0f);
    } else { o0 = 0.0f; o1 = 0.0f; }
    int i0 = (w >> 7) * FRAGH + fidxh(w & 127, c0);
    g_Ghf[i0] = pk2h(o0, o1);
    g_Glf[i0] = pk2h(o0 - hi16(o0), o1 - hi16(o1));
    if (hf == 0 && lane == 0) g_rf[w] = 0;
}

// 2 edges per thread, vectorized; trigger AFTER wait so k_gemm1's early launch
// implies gemm2 is fully complete (gates gemm1's pre-wait A-fragment reads)
__global__ void k_alpha(const int* __restrict__ ei, const float* __restrict__ bdec,
                        float* __restrict__ out, int it) {
    int e = (blockIdx.x * blockDim.x + threadIdx.x) * 2;
    if (e >= EE) { PDL_WAIT(); PDL_TRIGGER(); return; }
    int2 sv = *(const int2*)(ei + e);
    int2 dv = *(const int2*)(ei + EE + e);
    float bd = bdec[0];
    PDL_WAIT();   // a1/a2 from gemm2 gated here
    PDL_TRIGGER();
    float t0 = g_a1[sv.x] + g_a2[dv.x] + bd;
    float t1 = g_a1[sv.y] + g_a2[dv.y] + bd;
    float al0 = sigmoidf_fast(t0);
    float al1 = sigmoidf_fast(t1);
    float2 o = {al0, al1};
    *(float2*)(out + (size_t)it * EE + e) = o;
    if (al0 >= 0.4f) { g_rf[sv.x] = 1; g_rf[dv.x] = 1; }
    if (al1 >= 0.4f) { g_rf[sv.y] = 1; g_rf[dv.y] = 1; }
}

__global__ void k_final(const float* __restrict__ bdec, float* __restrict__ out) {
    int w = (blockIdx.x * blockDim.x + threadIdx.x) >> 5;
    int lane = threadIdx.x & 31;
    if (w >= NN) return;
    int beg = g_indptr[w], end = g_indptr[w + 1];
    float bd = bdec[0];
    PDL_WAIT();
    if (lane == 0) out[(size_t)10 * EE + w] = g_rf[w] ? 1.0f : 0.0f;
    float a2v = g_a2[w];
    float ba = -1.0f;
    int beid = 0x7FFFFFFF, bsrc = w;
    for (int j = beg + lane; j < end; j += 32) {
        int sv = g_csr_src[j], eid = g_csr_eid[j];
        float t = g_a1[sv] + a2v + bd;
        float al = sigmoidf_fast(t);
        if (al > ba || (al == ba && eid < beid)) { ba = al; beid = eid; bsrc = sv; }
    }
#pragma unroll
    for (int o = 16; o; o >>= 1) {
        float oa = __shfl_xor_sync(0xFFFFFFFFu, ba, o);
        int oe = __shfl_xor_sync(0xFFFFFFFFu, beid, o);
        int os = __shfl_xor_sync(0xFFFFFFFFu, bsrc, o);
        if (oa > ba || (oa == ba && oe < beid)) { ba = oa; beid = oe; bsrc = os; }
    }
    if (lane == 0) out[(size_t)10 * EE + NN + w] = (float)((end > beg) ? bsrc : w);
}

// ---------------- host ----------------
static void launch_pdl(const void* func, dim3 grid, dim3 block, size_t smem, void** args) {
    cudaLaunchConfig_t cfg = {};
    cfg.gridDim = grid;
    cfg.blockDim = block;
    cfg.dynamicSmemBytes = smem;
    cfg.stream = 0;
    cudaLaunchAttribute attr;
    attr.id = cudaLaunchAttributeProgrammaticStreamSerialization;
    attr.val.programmaticStreamSerializationAllowed = 1;
    cfg.attrs = &attr;
    cfg.numAttrs = 1;
    cudaLaunchKernelExC(&cfg, func, args);
}

extern "C" void kernel_launch(void* const* d_in, const int* in_sizes, int n_in,
                              void* d_out, int out_size) {
    const float* pos  = (const float*)d_in[0];
    const float* s    = (const float*)d_in[1];
    const int*   ei   = (const int*)d_in[2];
    const float* Wenc = (const float*)d_in[3];
    const float* benc = (const float*)d_in[4];
    const float* W1   = (const float*)d_in[5];
    const float* W2   = (const float*)d_in[6];
    const float* bmsg = (const float*)d_in[7];
    const float* Wout = (const float*)d_in[8];
    const float* bout = (const float*)d_in[9];
    const float* Wdec = (const float*)d_in[10];
    const float* bdec = (const float*)d_in[11];
    float* out = (float*)d_out;

    const int SMEM2 = 49152;
    cudaFuncSetAttribute(k_setupgemm, cudaFuncAttributeMaxDynamicSharedMemorySize, SMEM2);
    cudaFuncSetAttribute(k_gemm1, cudaFuncAttributeMaxDynamicSharedMemorySize, SMEM2);
    cudaFuncSetAttribute(k_gemm2, cudaFuncAttributeMaxDynamicSharedMemorySize, SMEM2);

    const int TB = 256;
    k_init<<<(NN + TB - 1) / TB, TB>>>();
    k_hist<<<(EE + TB - 1) / TB, TB>>>(ei);
    k_scan<<<1, 1024>>>();
    k_fused<<<1024, TB>>>(ei, W1, W2, Wout, pos, Wenc, benc);
    {
        void* args[] = {(void*)&s};
        launch_pdl((const void*)k_setupgemm, dim3(8 * MBK), dim3(TB), SMEM2, args);
    }

    for (int it = 0; it < ITERS; it++) {
        if (it > 0)
            launch_pdl((const void*)k_gemm1, dim3(2 * MBK, 2), dim3(TB), SMEM2, nullptr);
        {
            void* args[] = {(void*)&bmsg};
            launch_pdl((const void*)k_segmax, dim3((NN * 2 + 7) / 8), dim3(TB), 0, args);
        }
        {
            void* args[] = {(void*)&bout, (void*)&Wdec};
            launch_pdl((const void*)k_gemm2, dim3(2 * MBK), dim3(TB), SMEM2, args);
        }
        {
            int itv = it;
            void* args[] = {(void*)&ei, (void*)&bdec, (void*)&out, (void*)&itv};
            launch_pdl((const void*)k_alpha, dim3((EE / 2 + TB - 1) / TB), dim3(TB), 0, args);
        }
    }
    {
        void* args[] = {(void*)&bdec, (void*)&out};
        launch_pdl((const void*)k_final, dim3((NN + 7) / 8), dim3(TB), 0, args);
    }
}